// round 1
// baseline (speedup 1.0000x reference)
#include <cuda_runtime.h>
#include <math.h>

// Problem constants
#define BATCH   32
#define HDIM    64          // H
#define WDIM    64          // W
#define CDIM    256
#define WS      8
#define SS      4
#define HEADS   8
#define HD      32
#define WS2     64          // tokens per window
#define NWPI    64          // windows per image
#define NWIN    2048        // BATCH * NWPI
#define QKV_N   768
#define SCALE   0.17677669529663687f   // 32^-0.5

// Scratch (allocation-free rule: __device__ globals)
__device__ float g_qkv[(size_t)NWIN * WS2 * QKV_N];   // [win][tok][768]  q|k|v
__device__ float g_att[(size_t)NWIN * WS2 * CDIM];    // [win][tok][256]

// Shift/window <-> global row mapping. roll(-SS) gather and roll(+SS) scatter
// use the SAME index: (coord + SS) & 63.
__device__ __forceinline__ int global_row(int win, int m) {
    int b  = win >> 6;
    int wi = win & 63;
    int wy = wi >> 3, wx = wi & 7;
    int ty = m >> 3,  tx = m & 7;
    int sy = (wy * 8 + ty + SS) & 63;
    int sx = (wx * 8 + tx + SS) & 63;
    return b * (HDIM * WDIM) + sy * WDIM + sx;
}

// ---------------------------------------------------------------------------
// Kernel 1: QKV projection with fused shift+window gather.
// Per block: one window (M=64 tokens) x one 64-wide slice of the 768 outputs.
// K = 256 in 4 tiles of 64. 256 threads, 4x4 microtile each.
// ---------------------------------------------------------------------------
__global__ __launch_bounds__(256) void qkv_kernel(
    const float* __restrict__ x,      // [B*4096, 256]
    const float* __restrict__ w,      // [256, 768]
    const float* __restrict__ bias,   // [768]
    float* __restrict__ qkv)          // [NWIN, 64, 768]
{
    const int nblk = blockIdx.x;      // 0..11
    const int win  = blockIdx.y;      // 0..2047

    __shared__ float As[64][68];      // As[k][m] (transposed)
    __shared__ float Bs[64][68];      // Bs[k][n]

    const int tid = threadIdx.x;
    const int txn = tid & 15;         // N direction
    const int tym = tid >> 4;         // M direction

    float acc[4][4] = {};

    for (int kt = 0; kt < 4; kt++) {
        // Load A tile (gathered x rows), store transposed
        #pragma unroll
        for (int it = 0; it < 4; it++) {
            int m  = (tid >> 4) + it * 16;
            int k4 = tid & 15;
            int row = global_row(win, m);
            const float4 v = *(const float4*)(x + (size_t)row * CDIM + kt * 64 + k4 * 4);
            As[k4 * 4 + 0][m] = v.x;
            As[k4 * 4 + 1][m] = v.y;
            As[k4 * 4 + 2][m] = v.z;
            As[k4 * 4 + 3][m] = v.w;
        }
        // Load B tile
        #pragma unroll
        for (int it = 0; it < 4; it++) {
            int k  = (tid >> 4) + it * 16;
            int n4 = tid & 15;
            const float4 v = *(const float4*)(w + (size_t)(kt * 64 + k) * QKV_N + nblk * 64 + n4 * 4);
            *(float4*)&Bs[k][n4 * 4] = v;
        }
        __syncthreads();

        #pragma unroll
        for (int k = 0; k < 64; k++) {
            float a[4], b[4];
            *(float4*)a = *(const float4*)&As[k][tym * 4];
            *(float4*)b = *(const float4*)&Bs[k][txn * 4];
            #pragma unroll
            for (int i = 0; i < 4; i++)
                #pragma unroll
                for (int j = 0; j < 4; j++)
                    acc[i][j] += a[i] * b[j];
        }
        __syncthreads();
    }

    // Store + bias
    #pragma unroll
    for (int i = 0; i < 4; i++) {
        int m   = tym * 4 + i;
        int col = nblk * 64 + txn * 4;
        float4 o;
        o.x = acc[i][0] + bias[col + 0];
        o.y = acc[i][1] + bias[col + 1];
        o.z = acc[i][2] + bias[col + 2];
        o.w = acc[i][3] + bias[col + 3];
        *(float4*)(qkv + (size_t)win * WS2 * QKV_N + (size_t)m * QKV_N + col) = o;
    }
}

// ---------------------------------------------------------------------------
// Kernel 2: per-(window, head) attention.
// blockIdx.x = head, blockIdx.y = window. 256 threads.
// ---------------------------------------------------------------------------
__global__ __launch_bounds__(256) void attn_kernel(
    const float* __restrict__ qkv,    // [NWIN, 64, 768]
    const float* __restrict__ pos,    // [8, 225]
    float* __restrict__ att)          // [NWIN, 64, 256]
{
    const int h   = blockIdx.x;
    const int win = blockIdx.y;
    const int wi  = win & 63;
    const int wy  = wi >> 3, wx = wi & 7;

    __shared__ float qs[64][33];
    __shared__ float ks[64][33];
    __shared__ float vs[64][32];
    __shared__ float ps[64][65];
    __shared__ float pe[225];
    __shared__ float rinv[64];

    const int tid = threadIdx.x;

    // load q,k,v (64 x 32 each) for this head
    const size_t base = (size_t)win * WS2 * QKV_N + h * HD;
    #pragma unroll
    for (int it = 0; it < 2; it++) {
        int idx = tid + it * 256;            // 0..511
        int t   = idx >> 3;
        int d4  = idx & 7;
        float4 q4 = *(const float4*)(qkv + base + (size_t)t * QKV_N +           d4 * 4);
        float4 k4 = *(const float4*)(qkv + base + (size_t)t * QKV_N + CDIM    + d4 * 4);
        float4 v4 = *(const float4*)(qkv + base + (size_t)t * QKV_N + 2*CDIM  + d4 * 4);
        qs[t][d4*4+0]=q4.x; qs[t][d4*4+1]=q4.y; qs[t][d4*4+2]=q4.z; qs[t][d4*4+3]=q4.w;
        ks[t][d4*4+0]=k4.x; ks[t][d4*4+1]=k4.y; ks[t][d4*4+2]=k4.z; ks[t][d4*4+3]=k4.w;
        *(float4*)&vs[t][d4*4] = v4;
    }
    if (tid < 225) pe[tid] = pos[h * 225 + tid];
    __syncthreads();

    // scores: thread owns row q = tid/4, keys [(tid%4)*16, +16)
    const int q   = tid >> 2;
    const int kk0 = (tid & 3) * 16;
    const int qy  = q >> 3, qx = q & 7;

    // region label in shifted image coords
    int gy = wy * 8 + qy, gx = wx * 8 + qx;
    int rq = (gy < 56 ? 0 : (gy < 60 ? 1 : 2)) * 3 + (gx < 56 ? 0 : (gx < 60 ? 1 : 2));

    float qreg[32];
    #pragma unroll
    for (int d = 0; d < 32; d++) qreg[d] = qs[q][d];

    float val[16];
    float mx = -1e30f;
    #pragma unroll
    for (int kk = 0; kk < 16; kk++) {
        int k  = kk0 + kk;
        int ky = k >> 3, kx = k & 7;
        float s = 0.f;
        #pragma unroll
        for (int d = 0; d < 32; d++) s += qreg[d] * ks[k][d];
        s = s * SCALE + pe[(qy - ky + 7) * 15 + (qx - kx + 7)];
        int hy = wy * 8 + ky, hx = wx * 8 + kx;
        int rk = (hy < 56 ? 0 : (hy < 60 ? 1 : 2)) * 3 + (hx < 56 ? 0 : (hx < 60 ? 1 : 2));
        if (rk != rq) s = -1e30f;
        val[kk] = s;
        mx = fmaxf(mx, s);
    }
    // 4-lane max reduce (lanes 4q..4q+3 are contiguous within a warp)
    mx = fmaxf(mx, __shfl_xor_sync(0xffffffffu, mx, 1));
    mx = fmaxf(mx, __shfl_xor_sync(0xffffffffu, mx, 2));

    float sum = 0.f;
    #pragma unroll
    for (int kk = 0; kk < 16; kk++) {
        float e = __expf(val[kk] - mx);
        val[kk] = e;
        sum += e;
    }
    sum += __shfl_xor_sync(0xffffffffu, sum, 1);
    sum += __shfl_xor_sync(0xffffffffu, sum, 2);

    #pragma unroll
    for (int kk = 0; kk < 16; kk++) ps[q][kk0 + kk] = val[kk];
    if ((tid & 3) == 0) rinv[q] = 1.0f / sum;
    __syncthreads();

    // out = P @ V : thread owns (q, d0..d0+7)
    const int d0 = (tid & 3) * 8;
    float acc[8] = {};
    #pragma unroll 8
    for (int k = 0; k < 64; k++) {
        float pk = ps[q][k];
        #pragma unroll
        for (int j = 0; j < 8; j++) acc[j] += pk * vs[k][d0 + j];
    }
    float inv = rinv[q];
    float4 o0, o1;
    o0.x = acc[0]*inv; o0.y = acc[1]*inv; o0.z = acc[2]*inv; o0.w = acc[3]*inv;
    o1.x = acc[4]*inv; o1.y = acc[5]*inv; o1.z = acc[6]*inv; o1.w = acc[7]*inv;
    float* dst = att + (size_t)win * WS2 * CDIM + (size_t)q * CDIM + h * HD + d0;
    *(float4*)(dst)     = o0;
    *(float4*)(dst + 4) = o1;
}

// ---------------------------------------------------------------------------
// Kernel 3: output projection with fused reverse-window + reverse-shift scatter
// ---------------------------------------------------------------------------
__global__ __launch_bounds__(256) void outproj_kernel(
    const float* __restrict__ att,    // [NWIN, 64, 256]
    const float* __restrict__ w,      // [256, 256]
    const float* __restrict__ bias,   // [256]
    float* __restrict__ out)          // [B*4096, 256]
{
    const int nblk = blockIdx.x;      // 0..3
    const int win  = blockIdx.y;

    __shared__ float As[64][68];      // As[k][m]
    __shared__ float Bs[64][68];      // Bs[k][n]

    const int tid = threadIdx.x;
    const int txn = tid & 15;
    const int tym = tid >> 4;

    float acc[4][4] = {};

    for (int kt = 0; kt < 4; kt++) {
        #pragma unroll
        for (int it = 0; it < 4; it++) {
            int m  = (tid >> 4) + it * 16;
            int k4 = tid & 15;
            const float4 v = *(const float4*)(att + (size_t)win * WS2 * CDIM + (size_t)m * CDIM + kt * 64 + k4 * 4);
            As[k4 * 4 + 0][m] = v.x;
            As[k4 * 4 + 1][m] = v.y;
            As[k4 * 4 + 2][m] = v.z;
            As[k4 * 4 + 3][m] = v.w;
        }
        #pragma unroll
        for (int it = 0; it < 4; it++) {
            int k  = (tid >> 4) + it * 16;
            int n4 = tid & 15;
            const float4 v = *(const float4*)(w + (size_t)(kt * 64 + k) * CDIM + nblk * 64 + n4 * 4);
            *(float4*)&Bs[k][n4 * 4] = v;
        }
        __syncthreads();

        #pragma unroll
        for (int k = 0; k < 64; k++) {
            float a[4], b[4];
            *(float4*)a = *(const float4*)&As[k][tym * 4];
            *(float4*)b = *(const float4*)&Bs[k][txn * 4];
            #pragma unroll
            for (int i = 0; i < 4; i++)
                #pragma unroll
                for (int j = 0; j < 4; j++)
                    acc[i][j] += a[i] * b[j];
        }
        __syncthreads();
    }

    #pragma unroll
    for (int i = 0; i < 4; i++) {
        int m   = tym * 4 + i;
        int col = nblk * 64 + txn * 4;
        int row = global_row(win, m);
        float4 o;
        o.x = acc[i][0] + bias[col + 0];
        o.y = acc[i][1] + bias[col + 1];
        o.z = acc[i][2] + bias[col + 2];
        o.w = acc[i][3] + bias[col + 3];
        *(float4*)(out + (size_t)row * CDIM + col) = o;
    }
}

// ---------------------------------------------------------------------------
extern "C" void kernel_launch(void* const* d_in, const int* in_sizes, int n_in,
                              void* d_out, int out_size) {
    const float* x     = (const float*)d_in[0];
    const float* w_qkv = (const float*)d_in[1];
    const float* b_qkv = (const float*)d_in[2];
    const float* w_out = (const float*)d_in[3];
    const float* b_out = (const float*)d_in[4];
    const float* pos   = (const float*)d_in[5];
    float* out = (float*)d_out;

    float* qkv;
    float* att;
    cudaGetSymbolAddress((void**)&qkv, g_qkv);
    cudaGetSymbolAddress((void**)&att, g_att);

    qkv_kernel<<<dim3(12, NWIN), 256>>>(x, w_qkv, b_qkv, qkv);
    attn_kernel<<<dim3(HEADS, NWIN), 256>>>(qkv, pos, att);
    outproj_kernel<<<dim3(4, NWIN), 256>>>(att, w_out, b_out, out);
}

// round 3
// speedup vs baseline: 1.9147x; 1.9147x over previous
#include <cuda_runtime.h>
#include <cuda_bf16.h>
#include <math.h>
#include <stdint.h>

// Problem constants
#define BATCH   32
#define HDIM    64
#define WDIM    64
#define CDIM    256
#define WS      8
#define SS      4
#define HEADS   8
#define HD      32
#define WS2     64
#define NWPI    64
#define NWIN    2048
#define QKV_N   768
#define SCALE   0.17677669529663687f

// Scratch
__device__ float g_qkv[(size_t)NWIN * WS2 * QKV_N];
__device__ float g_att[(size_t)NWIN * WS2 * CDIM];
__device__ __nv_bfloat16 g_wq_hi[QKV_N * CDIM];   // [n][k]
__device__ __nv_bfloat16 g_wq_lo[QKV_N * CDIM];
__device__ __nv_bfloat16 g_wo_hi[CDIM * CDIM];
__device__ __nv_bfloat16 g_wo_lo[CDIM * CDIM];

// GEMM smem layout (dynamic)
#define OFF_AH    0
#define OFF_AL    16384
#define OFF_BH    32768
#define OFF_BL    49152
#define OFF_BIAS  67584          // after the 67584-byte epilogue stage
#define SMEM_GEMM 68096

__device__ __forceinline__ int global_row(int win, int m) {
    int b  = win >> 6;
    int wi = win & 63;
    int wy = wi >> 3, wx = wi & 7;
    int ty = m >> 3,  tx = m & 7;
    int sy = (wy * 8 + ty + SS) & 63;
    int sx = (wx * 8 + tx + SS) & 63;
    return b * (HDIM * WDIM) + sy * WDIM + sx;
}

__device__ __forceinline__ uint32_t smem_u32(const void* p) {
    uint32_t a;
    asm("{ .reg .u64 t; cvta.to.shared.u64 t, %1; cvt.u32.u64 %0, t; }" : "=r"(a) : "l"(p));
    return a;
}

__device__ __forceinline__ uint32_t sw128(uint32_t off) {
    return off ^ ((off >> 3) & 0x70);
}

__device__ __forceinline__ void ldsm4(uint32_t* r, uint32_t addr) {
    asm volatile("ldmatrix.sync.aligned.m8n8.x4.shared.b16 {%0,%1,%2,%3}, [%4];"
                 : "=r"(r[0]), "=r"(r[1]), "=r"(r[2]), "=r"(r[3]) : "r"(addr));
}
__device__ __forceinline__ void ldsm2(uint32_t* r, uint32_t addr) {
    asm volatile("ldmatrix.sync.aligned.m8n8.x2.shared.b16 {%0,%1}, [%2];"
                 : "=r"(r[0]), "=r"(r[1]) : "r"(addr));
}
__device__ __forceinline__ void mma16816(float* c, const uint32_t* a, const uint32_t* b) {
    asm volatile(
        "mma.sync.aligned.m16n8k16.row.col.f32.bf16.bf16.f32 "
        "{%0,%1,%2,%3}, {%4,%5,%6,%7}, {%8,%9}, {%0,%1,%2,%3};"
        : "+f"(c[0]), "+f"(c[1]), "+f"(c[2]), "+f"(c[3])
        : "r"(a[0]), "r"(a[1]), "r"(a[2]), "r"(a[3]), "r"(b[0]), "r"(b[1]));
}

// split a float4 into hi/lo bf16 and store 8B each to swizzled smem
__device__ __forceinline__ void split_store(char* smem, uint32_t off_hi, uint32_t off_lo,
                                            uint32_t byte_off, float4 v) {
    uint32_t sw = sw128(byte_off);
    __nv_bfloat162 h01 = __float22bfloat162_rn(make_float2(v.x, v.y));
    __nv_bfloat162 h23 = __float22bfloat162_rn(make_float2(v.z, v.w));
    float2 hf01 = __bfloat1622float2(h01);
    float2 hf23 = __bfloat1622float2(h23);
    __nv_bfloat162 l01 = __float22bfloat162_rn(make_float2(v.x - hf01.x, v.y - hf01.y));
    __nv_bfloat162 l23 = __float22bfloat162_rn(make_float2(v.z - hf23.x, v.w - hf23.y));
    uint2 hh, ll;
    hh.x = *(uint32_t*)&h01; hh.y = *(uint32_t*)&h23;
    ll.x = *(uint32_t*)&l01; ll.y = *(uint32_t*)&l23;
    *(uint2*)(smem + off_hi + sw) = hh;
    *(uint2*)(smem + off_lo + sw) = ll;
}

// ---------------------------------------------------------------------------
// HMMA GEMM: C[M=128/CTA, N=128/CTA] = A[.,256] * B^T, bf16 hi/lo 3-pass.
// NT: output row stride. GATHER: shift-gather A rows. SCATTER: shift-scatter out.
// ---------------------------------------------------------------------------
template<int NT, bool GATHER, bool SCATTER>
__global__ __launch_bounds__(256) void gemm_mma(
    const float* __restrict__ A,
    const __nv_bfloat16* __restrict__ Bhp,
    const __nv_bfloat16* __restrict__ Blp,
    const float* __restrict__ bias,
    float* __restrict__ out)
{
    extern __shared__ char smem[];
    const uint32_t sb = smem_u32(smem);
    const int tid = threadIdx.x, l = tid & 31, wid = tid >> 5;
    const int mt = blockIdx.x, nb = blockIdx.y;
    const int wm = wid >> 2, wn = wid & 3;

    float* bias_s = (float*)(smem + OFF_BIAS);
    if (tid < 128) bias_s[tid] = bias[nb * 128 + tid];

    // A source
    const int arow = tid >> 1;
    const int ac0  = (tid & 1) * 32;
    const int lr   = mt * 128 + arow;
    const int grow = GATHER ? global_row(lr >> 6, lr & 63) : lr;
    const float* asrc0 = A + (size_t)grow * CDIM + ac0;

    // ldmatrix lane geometry
    const int sub  = l >> 3;
    const int arl  = wm * 64 + (sub & 1) * 8 + (l & 7);   // A lane row (+mi*16)
    const int acb  = (sub >> 1) * 16;                     // A lane col byte (+k0b)
    const int lb   = l & 15;
    const int brl  = wn * 32 + (lb & 7);                  // B lane row (+ni*8)
    const int bcb  = (lb >> 3) * 16;                      // B lane col byte (+k0b)

    float acc[4][4][4];
    #pragma unroll
    for (int i = 0; i < 4; i++)
        #pragma unroll
        for (int j = 0; j < 4; j++)
            #pragma unroll
            for (int r = 0; r < 4; r++) acc[i][j][r] = 0.f;

    for (int kt = 0; kt < 4; kt++) {
        // stage A (split fp32 -> hi/lo bf16)
        const float* asrc = asrc0 + kt * 64;
        #pragma unroll
        for (int i = 0; i < 8; i++) {
            float4 v = *(const float4*)(asrc + i * 4);
            split_store(smem, OFF_AH, OFF_AL, arow * 128 + (ac0 + i * 4) * 2, v);
        }
        // stage B (precomputed bf16 hi/lo, [n][k] k-contig)
        #pragma unroll
        for (int it = 0; it < 4; it++) {
            int idx = it * 256 + tid;
            int br = idx >> 3, bc8 = (idx & 7) * 8;
            size_t goff = (size_t)(nb * 128 + br) * CDIM + kt * 64 + bc8;
            uint4 hv = *(const uint4*)(Bhp + goff);
            uint4 lv = *(const uint4*)(Blp + goff);
            uint32_t sw = sw128(br * 128 + bc8 * 2);
            *(uint4*)(smem + OFF_BH + sw) = hv;
            *(uint4*)(smem + OFF_BL + sw) = lv;
        }
        __syncthreads();

        #pragma unroll
        for (int k16 = 0; k16 < 4; k16++) {
            const int k0b = k16 * 32;
            uint32_t Bh[4][2], Bl[4][2];
            #pragma unroll
            for (int ni = 0; ni < 4; ni++) {
                uint32_t boff = sw128((brl + ni * 8) * 128 + k0b + bcb);
                ldsm2(Bh[ni], sb + OFF_BH + boff);
                ldsm2(Bl[ni], sb + OFF_BL + boff);
            }
            #pragma unroll
            for (int mi = 0; mi < 4; mi++) {
                uint32_t aoff = sw128((arl + mi * 16) * 128 + k0b + acb);
                uint32_t Ah[4], Al[4];
                ldsm4(Ah, sb + OFF_AH + aoff);
                ldsm4(Al, sb + OFF_AL + aoff);
                #pragma unroll
                for (int ni = 0; ni < 4; ni++) {
                    mma16816(acc[mi][ni], Ah, Bh[ni]);
                    mma16816(acc[mi][ni], Ah, Bl[ni]);
                    mma16816(acc[mi][ni], Al, Bh[ni]);
                }
            }
        }
        __syncthreads();
    }

    // epilogue: stage in smem, coalesced global store with bias
    float* stage = (float*)smem;
    #pragma unroll
    for (int mi = 0; mi < 4; mi++)
        #pragma unroll
        for (int ni = 0; ni < 4; ni++) {
            int row = wm * 64 + mi * 16 + (l >> 2);
            int col = wn * 32 + ni * 8 + (l & 3) * 2;
            float2 lo = make_float2(acc[mi][ni][0], acc[mi][ni][1]);
            float2 hi = make_float2(acc[mi][ni][2], acc[mi][ni][3]);
            *(float2*)&stage[row * 132 + col]       = lo;
            *(float2*)&stage[(row + 8) * 132 + col] = hi;
        }
    __syncthreads();

    #pragma unroll
    for (int it = 0; it < 16; it++) {
        int idx = it * 256 + tid;
        int row = idx >> 5, c4 = (idx & 31) * 4;
        float4 o;
        o.x = stage[row * 132 + c4 + 0] + bias_s[c4 + 0];
        o.y = stage[row * 132 + c4 + 1] + bias_s[c4 + 1];
        o.z = stage[row * 132 + c4 + 2] + bias_s[c4 + 2];
        o.w = stage[row * 132 + c4 + 3] + bias_s[c4 + 3];
        int lrow = mt * 128 + row;
        int orow = SCATTER ? global_row(lrow >> 6, lrow & 63) : lrow;
        *(float4*)(out + (size_t)orow * NT + nb * 128 + c4) = o;
    }
}

// ---------------------------------------------------------------------------
// Weight convert/transpose/split — grid (1024, 256 threads)
// ---------------------------------------------------------------------------
__global__ void convert_w(const float* __restrict__ wq, const float* __restrict__ wo) {
    int n = blockIdx.x, k = threadIdx.x;
    if (n < QKV_N) {
        float v = wq[k * QKV_N + n];
        __nv_bfloat16 h = __float2bfloat16(v);
        g_wq_hi[n * CDIM + k] = h;
        g_wq_lo[n * CDIM + k] = __float2bfloat16(v - __bfloat162float(h));
    } else {
        int n2 = n - QKV_N;
        float v = wo[k * CDIM + n2];
        __nv_bfloat16 h = __float2bfloat16(v);
        g_wo_hi[n2 * CDIM + k] = h;
        g_wo_lo[n2 * CDIM + k] = __float2bfloat16(v - __bfloat162float(h));
    }
}

// ---------------------------------------------------------------------------
// Attention: per (window, head). 2 q-rows x 8 keys per thread.
// ---------------------------------------------------------------------------
__global__ __launch_bounds__(256) void attn_kernel(
    const float* __restrict__ qkv, const float* __restrict__ pos,
    float* __restrict__ att)
{
    const int h   = blockIdx.x;
    const int win = blockIdx.y;
    const int wi  = win & 63;
    const int wy  = wi >> 3, wx = wi & 7;

    __shared__ float qs[64][33];
    __shared__ float ks[64][33];
    __shared__ float vs[64][33];
    __shared__ float ps[64][65];
    __shared__ float pe[225];
    __shared__ float rinv[64];

    const int tid = threadIdx.x;

    const size_t base = (size_t)win * WS2 * QKV_N + h * HD;
    #pragma unroll
    for (int it = 0; it < 2; it++) {
        int idx = tid + it * 256;
        int t   = idx >> 3;
        int d4  = idx & 7;
        float4 q4 = *(const float4*)(qkv + base + (size_t)t * QKV_N +            d4 * 4);
        float4 k4 = *(const float4*)(qkv + base + (size_t)t * QKV_N + CDIM     + d4 * 4);
        float4 v4 = *(const float4*)(qkv + base + (size_t)t * QKV_N + 2 * CDIM + d4 * 4);
        qs[t][d4*4+0]=q4.x; qs[t][d4*4+1]=q4.y; qs[t][d4*4+2]=q4.z; qs[t][d4*4+3]=q4.w;
        ks[t][d4*4+0]=k4.x; ks[t][d4*4+1]=k4.y; ks[t][d4*4+2]=k4.z; ks[t][d4*4+3]=k4.w;
        vs[t][d4*4+0]=v4.x; vs[t][d4*4+1]=v4.y; vs[t][d4*4+2]=v4.z; vs[t][d4*4+3]=v4.w;
    }
    if (tid < 225) pe[tid] = pos[h * 225 + tid];
    __syncthreads();

    const int q0  = (tid >> 3) << 1;
    const int kk0 = (tid & 7) * 8;
    const int qy  = q0 >> 3, qx0 = q0 & 7, qx1 = qx0 + 1;

    int gy  = wy * 8 + qy;
    int gx0 = wx * 8 + qx0;
    int gx1 = gx0 + 1;
    int ry  = (gy < 56 ? 0 : (gy < 60 ? 1 : 2)) * 3;
    int rq0 = ry + (gx0 < 56 ? 0 : (gx0 < 60 ? 1 : 2));
    int rq1 = ry + (gx1 < 56 ? 0 : (gx1 < 60 ? 1 : 2));

    float s[2][8];
    #pragma unroll
    for (int kk = 0; kk < 8; kk++) { s[0][kk] = 0.f; s[1][kk] = 0.f; }

    #pragma unroll 4
    for (int d = 0; d < 32; d++) {
        float qa = qs[q0][d], qb = qs[q0 + 1][d];
        #pragma unroll
        for (int kk = 0; kk < 8; kk++) {
            float kv = ks[kk0 + kk][d];
            s[0][kk] += qa * kv;
            s[1][kk] += qb * kv;
        }
    }

    float mx0 = -1e30f, mx1 = -1e30f;
    #pragma unroll
    for (int kk = 0; kk < 8; kk++) {
        int k  = kk0 + kk;
        int ky = k >> 3, kx = k & 7;
        int hy = wy * 8 + ky, hx = wx * 8 + kx;
        int rk = (hy < 56 ? 0 : (hy < 60 ? 1 : 2)) * 3 + (hx < 56 ? 0 : (hx < 60 ? 1 : 2));
        float b0 = pe[(qy - ky + 7) * 15 + (qx0 - kx + 7)];
        float b1 = pe[(qy - ky + 7) * 15 + (qx1 - kx + 7)];
        s[0][kk] = (rk == rq0) ? s[0][kk] * SCALE + b0 : -1e30f;
        s[1][kk] = (rk == rq1) ? s[1][kk] * SCALE + b1 : -1e30f;
        mx0 = fmaxf(mx0, s[0][kk]);
        mx1 = fmaxf(mx1, s[1][kk]);
    }
    mx0 = fmaxf(mx0, __shfl_xor_sync(0xffffffffu, mx0, 1));
    mx0 = fmaxf(mx0, __shfl_xor_sync(0xffffffffu, mx0, 2));
    mx0 = fmaxf(mx0, __shfl_xor_sync(0xffffffffu, mx0, 4));
    mx1 = fmaxf(mx1, __shfl_xor_sync(0xffffffffu, mx1, 1));
    mx1 = fmaxf(mx1, __shfl_xor_sync(0xffffffffu, mx1, 2));
    mx1 = fmaxf(mx1, __shfl_xor_sync(0xffffffffu, mx1, 4));

    float sum0 = 0.f, sum1 = 0.f;
    #pragma unroll
    for (int kk = 0; kk < 8; kk++) {
        float e0 = __expf(s[0][kk] - mx0);
        float e1 = __expf(s[1][kk] - mx1);
        s[0][kk] = e0; s[1][kk] = e1;
        sum0 += e0; sum1 += e1;
    }
    sum0 += __shfl_xor_sync(0xffffffffu, sum0, 1);
    sum0 += __shfl_xor_sync(0xffffffffu, sum0, 2);
    sum0 += __shfl_xor_sync(0xffffffffu, sum0, 4);
    sum1 += __shfl_xor_sync(0xffffffffu, sum1, 1);
    sum1 += __shfl_xor_sync(0xffffffffu, sum1, 2);
    sum1 += __shfl_xor_sync(0xffffffffu, sum1, 4);

    #pragma unroll
    for (int kk = 0; kk < 8; kk++) {
        ps[q0][kk0 + kk]     = s[0][kk];
        ps[q0 + 1][kk0 + kk] = s[1][kk];
    }
    if ((tid & 7) == 0) {
        rinv[q0]     = 1.0f / sum0;
        rinv[q0 + 1] = 1.0f / sum1;
    }
    __syncthreads();

    const int d0   = (tid & 3) * 8;
    const int kpar = (tid >> 2) & 1;

    float acc[2][8];
    #pragma unroll
    for (int j = 0; j < 8; j++) { acc[0][j] = 0.f; acc[1][j] = 0.f; }

    #pragma unroll 4
    for (int i = 0; i < 32; i++) {
        int k = 2 * i + kpar;
        float p0 = ps[q0][k], p1 = ps[q0 + 1][k];
        #pragma unroll
        for (int j = 0; j < 8; j++) {
            float v = vs[k][d0 + j];
            acc[0][j] += p0 * v;
            acc[1][j] += p1 * v;
        }
    }
    #pragma unroll
    for (int j = 0; j < 8; j++) {
        acc[0][j] += __shfl_xor_sync(0xffffffffu, acc[0][j], 4);
        acc[1][j] += __shfl_xor_sync(0xffffffffu, acc[1][j], 4);
    }

    if (kpar == 0) {
        float inv0 = rinv[q0], inv1 = rinv[q0 + 1];
        float* dst0 = att + (size_t)win * WS2 * CDIM + (size_t)q0 * CDIM + h * HD + d0;
        float* dst1 = dst0 + CDIM;
        float4 a, b;
        a.x = acc[0][0]*inv0; a.y = acc[0][1]*inv0; a.z = acc[0][2]*inv0; a.w = acc[0][3]*inv0;
        b.x = acc[0][4]*inv0; b.y = acc[0][5]*inv0; b.z = acc[0][6]*inv0; b.w = acc[0][7]*inv0;
        *(float4*)(dst0)     = a;
        *(float4*)(dst0 + 4) = b;
        a.x = acc[1][0]*inv1; a.y = acc[1][1]*inv1; a.z = acc[1][2]*inv1; a.w = acc[1][3]*inv1;
        b.x = acc[1][4]*inv1; b.y = acc[1][5]*inv1; b.z = acc[1][6]*inv1; b.w = acc[1][7]*inv1;
        *(float4*)(dst1)     = a;
        *(float4*)(dst1 + 4) = b;
    }
}

// ---------------------------------------------------------------------------
extern "C" void kernel_launch(void* const* d_in, const int* in_sizes, int n_in,
                              void* d_out, int out_size) {
    const float* x     = (const float*)d_in[0];
    const float* w_qkv = (const float*)d_in[1];
    const float* b_qkv = (const float*)d_in[2];
    const float* w_out = (const float*)d_in[3];
    const float* b_out = (const float*)d_in[4];
    const float* pos   = (const float*)d_in[5];
    float* out = (float*)d_out;

    float* qkv;  float* att;
    __nv_bfloat16 *wqh, *wql, *woh, *wol;
    cudaGetSymbolAddress((void**)&qkv, g_qkv);
    cudaGetSymbolAddress((void**)&att, g_att);
    cudaGetSymbolAddress((void**)&wqh, g_wq_hi);
    cudaGetSymbolAddress((void**)&wql, g_wq_lo);
    cudaGetSymbolAddress((void**)&woh, g_wo_hi);
    cudaGetSymbolAddress((void**)&wol, g_wo_lo);

    cudaFuncSetAttribute(gemm_mma<QKV_N, true,  false>,
                         cudaFuncAttributeMaxDynamicSharedMemorySize, SMEM_GEMM);
    cudaFuncSetAttribute(gemm_mma<CDIM,  false, true>,
                         cudaFuncAttributeMaxDynamicSharedMemorySize, SMEM_GEMM);

    convert_w<<<1024, 256>>>(w_qkv, w_out);
    gemm_mma<QKV_N, true,  false><<<dim3(1024, 6), 256, SMEM_GEMM>>>(x, wqh, wql, b_qkv, qkv);
    attn_kernel<<<dim3(HEADS, NWIN), 256>>>(qkv, pos, att);
    gemm_mma<CDIM,  false, true ><<<dim3(1024, 2), 256, SMEM_GEMM>>>(att, woh, wol, b_out, out);
}

// round 4
// speedup vs baseline: 2.4828x; 1.2967x over previous
#include <cuda_runtime.h>
#include <cuda_bf16.h>
#include <math.h>
#include <stdint.h>

// Problem constants
#define BATCH   32
#define HDIM    64
#define WDIM    64
#define CDIM    256
#define WS      8
#define SS      4
#define HEADS   8
#define HD      32
#define WS2     64
#define NWPI    64
#define NWIN    2048
#define QKV_N   768
#define MROWS   (NWIN * WS2)          // 131072
#define SCALE   0.17677669529663687f

// Scratch
__device__ float g_qkv[(size_t)MROWS * QKV_N];              // fp32 [win*64][768]
__device__ __nv_bfloat16 g_x_hi[(size_t)MROWS * CDIM];      // window-ordered, split
__device__ __nv_bfloat16 g_x_lo[(size_t)MROWS * CDIM];
__device__ __nv_bfloat16 g_att_hi[(size_t)MROWS * CDIM];
__device__ __nv_bfloat16 g_att_lo[(size_t)MROWS * CDIM];
__device__ __nv_bfloat16 g_wq_hi[QKV_N * CDIM];             // [n][k]
__device__ __nv_bfloat16 g_wq_lo[QKV_N * CDIM];
__device__ __nv_bfloat16 g_wo_hi[CDIM * CDIM];
__device__ __nv_bfloat16 g_wo_lo[CDIM * CDIM];

// GEMM smem: 2 stages x {AH, AL, BH, BL} x 16KB
#define STAGE_STRIDE 65536
#define OFF_AH    0
#define OFF_AL    16384
#define OFF_BH    32768
#define OFF_BL    49152
#define OFF_BIAS  131072
#define SMEM_GEMM 131648

__device__ __forceinline__ int global_row(int win, int m) {
    int b  = win >> 6;
    int wi = win & 63;
    int wy = wi >> 3, wx = wi & 7;
    int ty = m >> 3,  tx = m & 7;
    int sy = (wy * 8 + ty + SS) & 63;
    int sx = (wx * 8 + tx + SS) & 63;
    return b * (HDIM * WDIM) + sy * WDIM + sx;
}

__device__ __forceinline__ uint32_t smem_u32(const void* p) {
    uint32_t a;
    asm("{ .reg .u64 t; cvta.to.shared.u64 t, %1; cvt.u32.u64 %0, t; }" : "=r"(a) : "l"(p));
    return a;
}
__device__ __forceinline__ uint32_t sw128(uint32_t off) {
    return off ^ ((off >> 3) & 0x70);
}
__device__ __forceinline__ void cp16(uint32_t dst, const void* src) {
    asm volatile("cp.async.cg.shared.global [%0], [%1], 16;" :: "r"(dst), "l"(src));
}
__device__ __forceinline__ void ldsm4(uint32_t* r, uint32_t addr) {
    asm volatile("ldmatrix.sync.aligned.m8n8.x4.shared.b16 {%0,%1,%2,%3}, [%4];"
                 : "=r"(r[0]), "=r"(r[1]), "=r"(r[2]), "=r"(r[3]) : "r"(addr));
}
__device__ __forceinline__ void ldsm2(uint32_t* r, uint32_t addr) {
    asm volatile("ldmatrix.sync.aligned.m8n8.x2.shared.b16 {%0,%1}, [%2];"
                 : "=r"(r[0]), "=r"(r[1]) : "r"(addr));
}
__device__ __forceinline__ void mma16816(float* c, const uint32_t* a, const uint32_t* b) {
    asm volatile(
        "mma.sync.aligned.m16n8k16.row.col.f32.bf16.bf16.f32 "
        "{%0,%1,%2,%3}, {%4,%5,%6,%7}, {%8,%9}, {%0,%1,%2,%3};"
        : "+f"(c[0]), "+f"(c[1]), "+f"(c[2]), "+f"(c[3])
        : "r"(a[0]), "r"(a[1]), "r"(a[2]), "r"(a[3]), "r"(b[0]), "r"(b[1]));
}

// split 2 floats -> packed hi bf16x2 and lo bf16x2
__device__ __forceinline__ void split2(float a, float b, uint32_t& h, uint32_t& l) {
    __nv_bfloat162 hh = __float22bfloat162_rn(make_float2(a, b));
    float2 hf = __bfloat1622float2(hh);
    __nv_bfloat162 ll = __float22bfloat162_rn(make_float2(a - hf.x, b - hf.y));
    h = *(uint32_t*)&hh;
    l = *(uint32_t*)&ll;
}

// ---------------------------------------------------------------------------
// Pipelined bf16 hi/lo HMMA GEMM. 128x128 CTA tile, K=256 in 4 stages of 64.
// A is window-ordered bf16 hi/lo; optional shift-scatter on output rows.
// ---------------------------------------------------------------------------
template<int NT, bool SCATTER>
__global__ __launch_bounds__(256) void gemm_mma(
    const __nv_bfloat16* __restrict__ Ah, const __nv_bfloat16* __restrict__ Al,
    const __nv_bfloat16* __restrict__ Bh, const __nv_bfloat16* __restrict__ Bl,
    const float* __restrict__ bias, float* __restrict__ out)
{
    extern __shared__ char smem[];
    const uint32_t sb = smem_u32(smem);
    const int tid = threadIdx.x, l = tid & 31, wid = tid >> 5;
    const int mt = blockIdx.x, nb = blockIdx.y;
    const int wm = wid >> 2, wn = wid & 3;

    float* bias_s = (float*)(smem + OFF_BIAS);
    if (tid < 128) bias_s[tid] = bias[nb * 128 + tid];

    // per-thread cp.async geometry: i-th chunk covers row i*32+(tid>>3), col16 tid&7
    const int crow = tid >> 3;          // 0..31 (+ i*32)
    const int cc   = tid & 7;           // 16B chunk in row
    uint32_t sm_off[4];
    #pragma unroll
    for (int i = 0; i < 4; i++)
        sm_off[i] = sw128((i * 32 + crow) * 128 + cc * 16);

    const __nv_bfloat16* pAh = Ah + (size_t)(mt * 128 + crow) * CDIM + cc * 8;
    const __nv_bfloat16* pAl = Al + (size_t)(mt * 128 + crow) * CDIM + cc * 8;
    const __nv_bfloat16* pBh = Bh + (size_t)(nb * 128 + crow) * CDIM + cc * 8;
    const __nv_bfloat16* pBl = Bl + (size_t)(nb * 128 + crow) * CDIM + cc * 8;

    // ldmatrix lane geometry
    const int sub  = l >> 3;
    const int arl  = wm * 64 + (sub & 1) * 8 + (l & 7);
    const int acb  = (sub >> 1) * 16;
    const int lb   = l & 15;
    const int brl  = wn * 32 + (lb & 7);
    const int bcb  = (lb >> 3) * 16;

    float acc[4][4][4];
    #pragma unroll
    for (int i = 0; i < 4; i++)
        #pragma unroll
        for (int j = 0; j < 4; j++)
            #pragma unroll
            for (int r = 0; r < 4; r++) acc[i][j][r] = 0.f;

    // prefetch kt = 0 into stage 0
    {
        uint32_t base = sb;
        #pragma unroll
        for (int i = 0; i < 4; i++) {
            size_t g = (size_t)i * 32 * CDIM;
            cp16(base + OFF_AH + sm_off[i], pAh + g);
            cp16(base + OFF_AL + sm_off[i], pAl + g);
            cp16(base + OFF_BH + sm_off[i], pBh + g);
            cp16(base + OFF_BL + sm_off[i], pBl + g);
        }
        asm volatile("cp.async.commit_group;");
    }

    for (int kt = 0; kt < 4; kt++) {
        if (kt < 3) {
            uint32_t base = sb + ((kt + 1) & 1) * STAGE_STRIDE;
            size_t kadv = (size_t)(kt + 1) * 64;
            #pragma unroll
            for (int i = 0; i < 4; i++) {
                size_t g = (size_t)i * 32 * CDIM + kadv;
                cp16(base + OFF_AH + sm_off[i], pAh + g);
                cp16(base + OFF_AL + sm_off[i], pAl + g);
                cp16(base + OFF_BH + sm_off[i], pBh + g);
                cp16(base + OFF_BL + sm_off[i], pBl + g);
            }
            asm volatile("cp.async.commit_group;");
            asm volatile("cp.async.wait_group 1;");
        } else {
            asm volatile("cp.async.wait_group 0;");
        }
        __syncthreads();

        const uint32_t cbase = sb + (kt & 1) * STAGE_STRIDE;
        #pragma unroll
        for (int k16 = 0; k16 < 4; k16++) {
            const int k0b = k16 * 32;
            uint32_t Bhf[4][2], Blf[4][2];
            #pragma unroll
            for (int ni = 0; ni < 4; ni++) {
                uint32_t boff = sw128((brl + ni * 8) * 128 + k0b + bcb);
                ldsm2(Bhf[ni], cbase + OFF_BH + boff);
                ldsm2(Blf[ni], cbase + OFF_BL + boff);
            }
            #pragma unroll
            for (int mi = 0; mi < 4; mi++) {
                uint32_t aoff = sw128((arl + mi * 16) * 128 + k0b + acb);
                uint32_t Ahf[4], Alf[4];
                ldsm4(Ahf, cbase + OFF_AH + aoff);
                ldsm4(Alf, cbase + OFF_AL + aoff);
                #pragma unroll
                for (int ni = 0; ni < 4; ni++) {
                    mma16816(acc[mi][ni], Ahf, Bhf[ni]);
                    mma16816(acc[mi][ni], Ahf, Blf[ni]);
                    mma16816(acc[mi][ni], Alf, Bhf[ni]);
                }
            }
        }
        __syncthreads();
    }

    // epilogue: stage in smem, coalesced global store with bias
    float* stage = (float*)smem;
    #pragma unroll
    for (int mi = 0; mi < 4; mi++)
        #pragma unroll
        for (int ni = 0; ni < 4; ni++) {
            int row = wm * 64 + mi * 16 + (l >> 2);
            int col = wn * 32 + ni * 8 + (l & 3) * 2;
            *(float2*)&stage[row * 132 + col]       = make_float2(acc[mi][ni][0], acc[mi][ni][1]);
            *(float2*)&stage[(row + 8) * 132 + col] = make_float2(acc[mi][ni][2], acc[mi][ni][3]);
        }
    __syncthreads();

    #pragma unroll
    for (int it = 0; it < 16; it++) {
        int idx = it * 256 + tid;
        int row = idx >> 5, c4 = (idx & 31) * 4;
        float4 o;
        o.x = stage[row * 132 + c4 + 0] + bias_s[c4 + 0];
        o.y = stage[row * 132 + c4 + 1] + bias_s[c4 + 1];
        o.z = stage[row * 132 + c4 + 2] + bias_s[c4 + 2];
        o.w = stage[row * 132 + c4 + 3] + bias_s[c4 + 3];
        int lrow = mt * 128 + row;
        int orow = SCATTER ? global_row(lrow >> 6, lrow & 63) : lrow;
        *(float4*)(out + (size_t)orow * NT + nb * 128 + c4) = o;
    }
}

// ---------------------------------------------------------------------------
// Pre-pass: gather x into window order and split to bf16 hi/lo
// ---------------------------------------------------------------------------
__global__ __launch_bounds__(256) void convert_x(const float* __restrict__ x) {
    const int win = blockIdx.x;
    const int tid = threadIdx.x;
    #pragma unroll
    for (int i = 0; i < 16; i++) {
        int idx4 = i * 256 + tid;                // 0..4095 float4s
        int row  = idx4 >> 6;                    // 0..63
        int c4   = idx4 & 63;
        int grow = global_row(win, row);
        float4 v = *(const float4*)(x + (size_t)grow * CDIM + c4 * 4);
        uint32_t h0, h1, l0, l1;
        split2(v.x, v.y, h0, l0);
        split2(v.z, v.w, h1, l1);
        size_t o = ((size_t)win * WS2 + row) * CDIM + c4 * 4;
        *(uint2*)(g_x_hi + o) = make_uint2(h0, h1);
        *(uint2*)(g_x_lo + o) = make_uint2(l0, l1);
    }
}

// ---------------------------------------------------------------------------
// Weight convert/transpose/split — grid (1024, 256 threads)
// ---------------------------------------------------------------------------
__global__ void convert_w(const float* __restrict__ wq, const float* __restrict__ wo) {
    int n = blockIdx.x, k = threadIdx.x;
    if (n < QKV_N) {
        float v = wq[k * QKV_N + n];
        __nv_bfloat16 h = __float2bfloat16(v);
        g_wq_hi[n * CDIM + k] = h;
        g_wq_lo[n * CDIM + k] = __float2bfloat16(v - __bfloat162float(h));
    } else {
        int n2 = n - QKV_N;
        float v = wo[k * CDIM + n2];
        __nv_bfloat16 h = __float2bfloat16(v);
        g_wo_hi[n2 * CDIM + k] = h;
        g_wo_lo[n2 * CDIM + k] = __float2bfloat16(v - __bfloat162float(h));
    }
}

// ---------------------------------------------------------------------------
// Attention: per (window, head). Outputs split bf16 hi/lo.
// ---------------------------------------------------------------------------
__global__ __launch_bounds__(256) void attn_kernel(
    const float* __restrict__ qkv, const float* __restrict__ pos)
{
    const int h   = blockIdx.x;
    const int win = blockIdx.y;
    const int wi  = win & 63;
    const int wy  = wi >> 3, wx = wi & 7;

    __shared__ float qs[64][33];
    __shared__ float ks[64][33];
    __shared__ float vs[64][33];
    __shared__ float ps[64][65];
    __shared__ float pe[225];
    __shared__ float rinv[64];

    const int tid = threadIdx.x;

    const size_t base = (size_t)win * WS2 * QKV_N + h * HD;
    #pragma unroll
    for (int it = 0; it < 2; it++) {
        int idx = tid + it * 256;
        int t   = idx >> 3;
        int d4  = idx & 7;
        float4 q4 = *(const float4*)(qkv + base + (size_t)t * QKV_N +            d4 * 4);
        float4 k4 = *(const float4*)(qkv + base + (size_t)t * QKV_N + CDIM     + d4 * 4);
        float4 v4 = *(const float4*)(qkv + base + (size_t)t * QKV_N + 2 * CDIM + d4 * 4);
        qs[t][d4*4+0]=q4.x; qs[t][d4*4+1]=q4.y; qs[t][d4*4+2]=q4.z; qs[t][d4*4+3]=q4.w;
        ks[t][d4*4+0]=k4.x; ks[t][d4*4+1]=k4.y; ks[t][d4*4+2]=k4.z; ks[t][d4*4+3]=k4.w;
        vs[t][d4*4+0]=v4.x; vs[t][d4*4+1]=v4.y; vs[t][d4*4+2]=v4.z; vs[t][d4*4+3]=v4.w;
    }
    if (tid < 225) pe[tid] = pos[h * 225 + tid];
    __syncthreads();

    const int q0  = (tid >> 3) << 1;
    const int kk0 = (tid & 7) * 8;
    const int qy  = q0 >> 3, qx0 = q0 & 7, qx1 = qx0 + 1;

    int gy  = wy * 8 + qy;
    int gx0 = wx * 8 + qx0;
    int gx1 = gx0 + 1;
    int ry  = (gy < 56 ? 0 : (gy < 60 ? 1 : 2)) * 3;
    int rq0 = ry + (gx0 < 56 ? 0 : (gx0 < 60 ? 1 : 2));
    int rq1 = ry + (gx1 < 56 ? 0 : (gx1 < 60 ? 1 : 2));

    float s[2][8];
    #pragma unroll
    for (int kk = 0; kk < 8; kk++) { s[0][kk] = 0.f; s[1][kk] = 0.f; }

    #pragma unroll 4
    for (int d = 0; d < 32; d++) {
        float qa = qs[q0][d], qb = qs[q0 + 1][d];
        #pragma unroll
        for (int kk = 0; kk < 8; kk++) {
            float kv = ks[kk0 + kk][d];
            s[0][kk] += qa * kv;
            s[1][kk] += qb * kv;
        }
    }

    float mx0 = -1e30f, mx1 = -1e30f;
    #pragma unroll
    for (int kk = 0; kk < 8; kk++) {
        int k  = kk0 + kk;
        int ky = k >> 3, kx = k & 7;
        int hy = wy * 8 + ky, hx = wx * 8 + kx;
        int rk = (hy < 56 ? 0 : (hy < 60 ? 1 : 2)) * 3 + (hx < 56 ? 0 : (hx < 60 ? 1 : 2));
        float b0 = pe[(qy - ky + 7) * 15 + (qx0 - kx + 7)];
        float b1 = pe[(qy - ky + 7) * 15 + (qx1 - kx + 7)];
        s[0][kk] = (rk == rq0) ? s[0][kk] * SCALE + b0 : -1e30f;
        s[1][kk] = (rk == rq1) ? s[1][kk] * SCALE + b1 : -1e30f;
        mx0 = fmaxf(mx0, s[0][kk]);
        mx1 = fmaxf(mx1, s[1][kk]);
    }
    mx0 = fmaxf(mx0, __shfl_xor_sync(0xffffffffu, mx0, 1));
    mx0 = fmaxf(mx0, __shfl_xor_sync(0xffffffffu, mx0, 2));
    mx0 = fmaxf(mx0, __shfl_xor_sync(0xffffffffu, mx0, 4));
    mx1 = fmaxf(mx1, __shfl_xor_sync(0xffffffffu, mx1, 1));
    mx1 = fmaxf(mx1, __shfl_xor_sync(0xffffffffu, mx1, 2));
    mx1 = fmaxf(mx1, __shfl_xor_sync(0xffffffffu, mx1, 4));

    float sum0 = 0.f, sum1 = 0.f;
    #pragma unroll
    for (int kk = 0; kk < 8; kk++) {
        float e0 = __expf(s[0][kk] - mx0);
        float e1 = __expf(s[1][kk] - mx1);
        s[0][kk] = e0; s[1][kk] = e1;
        sum0 += e0; sum1 += e1;
    }
    sum0 += __shfl_xor_sync(0xffffffffu, sum0, 1);
    sum0 += __shfl_xor_sync(0xffffffffu, sum0, 2);
    sum0 += __shfl_xor_sync(0xffffffffu, sum0, 4);
    sum1 += __shfl_xor_sync(0xffffffffu, sum1, 1);
    sum1 += __shfl_xor_sync(0xffffffffu, sum1, 2);
    sum1 += __shfl_xor_sync(0xffffffffu, sum1, 4);

    #pragma unroll
    for (int kk = 0; kk < 8; kk++) {
        ps[q0][kk0 + kk]     = s[0][kk];
        ps[q0 + 1][kk0 + kk] = s[1][kk];
    }
    if ((tid & 7) == 0) {
        rinv[q0]     = 1.0f / sum0;
        rinv[q0 + 1] = 1.0f / sum1;
    }
    __syncthreads();

    const int d0   = (tid & 3) * 8;
    const int kpar = (tid >> 2) & 1;

    float acc[2][8];
    #pragma unroll
    for (int j = 0; j < 8; j++) { acc[0][j] = 0.f; acc[1][j] = 0.f; }

    #pragma unroll 4
    for (int i = 0; i < 32; i++) {
        int k = 2 * i + kpar;
        float p0 = ps[q0][k], p1 = ps[q0 + 1][k];
        #pragma unroll
        for (int j = 0; j < 8; j++) {
            float v = vs[k][d0 + j];
            acc[0][j] += p0 * v;
            acc[1][j] += p1 * v;
        }
    }
    #pragma unroll
    for (int j = 0; j < 8; j++) {
        acc[0][j] += __shfl_xor_sync(0xffffffffu, acc[0][j], 4);
        acc[1][j] += __shfl_xor_sync(0xffffffffu, acc[1][j], 4);
    }

    if (kpar == 0) {
        float inv0 = rinv[q0], inv1 = rinv[q0 + 1];
        size_t off0 = ((size_t)win * WS2 + q0) * CDIM + h * HD + d0;
        uint32_t hh[4], ll[4];
        #pragma unroll
        for (int i = 0; i < 4; i++)
            split2(acc[0][2*i] * inv0, acc[0][2*i+1] * inv0, hh[i], ll[i]);
        *(uint4*)(g_att_hi + off0) = make_uint4(hh[0], hh[1], hh[2], hh[3]);
        *(uint4*)(g_att_lo + off0) = make_uint4(ll[0], ll[1], ll[2], ll[3]);
        #pragma unroll
        for (int i = 0; i < 4; i++)
            split2(acc[1][2*i] * inv1, acc[1][2*i+1] * inv1, hh[i], ll[i]);
        *(uint4*)(g_att_hi + off0 + CDIM) = make_uint4(hh[0], hh[1], hh[2], hh[3]);
        *(uint4*)(g_att_lo + off0 + CDIM) = make_uint4(ll[0], ll[1], ll[2], ll[3]);
    }
}

// ---------------------------------------------------------------------------
extern "C" void kernel_launch(void* const* d_in, const int* in_sizes, int n_in,
                              void* d_out, int out_size) {
    const float* x     = (const float*)d_in[0];
    const float* w_qkv = (const float*)d_in[1];
    const float* b_qkv = (const float*)d_in[2];
    const float* w_out = (const float*)d_in[3];
    const float* b_out = (const float*)d_in[4];
    const float* pos   = (const float*)d_in[5];
    float* out = (float*)d_out;

    float* qkv;
    __nv_bfloat16 *xh, *xl, *ah, *al, *wqh, *wql, *woh, *wol;
    cudaGetSymbolAddress((void**)&qkv, g_qkv);
    cudaGetSymbolAddress((void**)&xh,  g_x_hi);
    cudaGetSymbolAddress((void**)&xl,  g_x_lo);
    cudaGetSymbolAddress((void**)&ah,  g_att_hi);
    cudaGetSymbolAddress((void**)&al,  g_att_lo);
    cudaGetSymbolAddress((void**)&wqh, g_wq_hi);
    cudaGetSymbolAddress((void**)&wql, g_wq_lo);
    cudaGetSymbolAddress((void**)&woh, g_wo_hi);
    cudaGetSymbolAddress((void**)&wol, g_wo_lo);

    cudaFuncSetAttribute(gemm_mma<QKV_N, false>,
                         cudaFuncAttributeMaxDynamicSharedMemorySize, SMEM_GEMM);
    cudaFuncSetAttribute(gemm_mma<CDIM,  true>,
                         cudaFuncAttributeMaxDynamicSharedMemorySize, SMEM_GEMM);

    convert_w<<<1024, 256>>>(w_qkv, w_out);
    convert_x<<<NWIN, 256>>>(x);
    gemm_mma<QKV_N, false><<<dim3(1024, 6), 256, SMEM_GEMM>>>(xh, xl, wqh, wql, b_qkv, qkv);
    attn_kernel<<<dim3(HEADS, NWIN), 256>>>(qkv, pos);
    gemm_mma<CDIM, true><<<dim3(1024, 2), 256, SMEM_GEMM>>>(ah, al, woh, wol, b_out, out);
}

// round 5
// speedup vs baseline: 3.5776x; 1.4410x over previous
#include <cuda_runtime.h>
#include <cuda_bf16.h>
#include <math.h>
#include <stdint.h>

// Problem constants
#define BATCH   32
#define HDIM    64
#define WDIM    64
#define CDIM    256
#define WS      8
#define SS      4
#define HEADS   8
#define HD      32
#define WS2     64
#define NWPI    64
#define NWIN    2048
#define QKV_N   768
#define MROWS   (NWIN * WS2)          // 131072
#define SCALE   0.17677669529663687f

// Scratch
__device__ __nv_bfloat16 g_qkv_hi[(size_t)MROWS * QKV_N];
__device__ __nv_bfloat16 g_qkv_lo[(size_t)MROWS * QKV_N];
__device__ __nv_bfloat16 g_x_hi[(size_t)MROWS * CDIM];      // window-ordered, split
__device__ __nv_bfloat16 g_x_lo[(size_t)MROWS * CDIM];
__device__ __nv_bfloat16 g_att_hi[(size_t)MROWS * CDIM];
__device__ __nv_bfloat16 g_att_lo[(size_t)MROWS * CDIM];
__device__ __nv_bfloat16 g_wq_hi[QKV_N * CDIM];             // [n][k]
__device__ __nv_bfloat16 g_wq_lo[QKV_N * CDIM];
__device__ __nv_bfloat16 g_wo_hi[CDIM * CDIM];
__device__ __nv_bfloat16 g_wo_lo[CDIM * CDIM];

// GEMM smem: 2 stages x {AH, AL, BH, BL} x 16KB
#define STAGE_STRIDE 65536
#define OFF_AH    0
#define OFF_AL    16384
#define OFF_BH    32768
#define OFF_BL    49152
#define OFF_BIAS  131072
#define SMEM_GEMM 131648

// Attention smem: per local head {Q 8K | K 8K | V 8K}, then pe
#define ATT_HSTRIDE 24576
#define ATT_PE_OFF  49152
#define SMEM_ATT    51200

__device__ __forceinline__ int global_row(int win, int m) {
    int b  = win >> 6;
    int wi = win & 63;
    int wy = wi >> 3, wx = wi & 7;
    int ty = m >> 3,  tx = m & 7;
    int sy = (wy * 8 + ty + SS) & 63;
    int sx = (wx * 8 + tx + SS) & 63;
    return b * (HDIM * WDIM) + sy * WDIM + sx;
}

__device__ __forceinline__ uint32_t smem_u32(const void* p) {
    uint32_t a;
    asm("{ .reg .u64 t; cvta.to.shared.u64 t, %1; cvt.u32.u64 %0, t; }" : "=r"(a) : "l"(p));
    return a;
}
__device__ __forceinline__ uint32_t sw128(uint32_t off) {
    return off ^ ((off >> 3) & 0x70);
}
__device__ __forceinline__ void cp16(uint32_t dst, const void* src) {
    asm volatile("cp.async.cg.shared.global [%0], [%1], 16;" :: "r"(dst), "l"(src));
}
__device__ __forceinline__ void ldsm4(uint32_t* r, uint32_t addr) {
    asm volatile("ldmatrix.sync.aligned.m8n8.x4.shared.b16 {%0,%1,%2,%3}, [%4];"
                 : "=r"(r[0]), "=r"(r[1]), "=r"(r[2]), "=r"(r[3]) : "r"(addr));
}
__device__ __forceinline__ void ldsm2(uint32_t* r, uint32_t addr) {
    asm volatile("ldmatrix.sync.aligned.m8n8.x2.shared.b16 {%0,%1}, [%2];"
                 : "=r"(r[0]), "=r"(r[1]) : "r"(addr));
}
__device__ __forceinline__ void ldsm2t(uint32_t* r, uint32_t addr) {
    asm volatile("ldmatrix.sync.aligned.m8n8.x2.trans.shared.b16 {%0,%1}, [%2];"
                 : "=r"(r[0]), "=r"(r[1]) : "r"(addr));
}
__device__ __forceinline__ void mma16816(float* c, const uint32_t* a, const uint32_t* b) {
    asm volatile(
        "mma.sync.aligned.m16n8k16.row.col.f32.bf16.bf16.f32 "
        "{%0,%1,%2,%3}, {%4,%5,%6,%7}, {%8,%9}, {%0,%1,%2,%3};"
        : "+f"(c[0]), "+f"(c[1]), "+f"(c[2]), "+f"(c[3])
        : "r"(a[0]), "r"(a[1]), "r"(a[2]), "r"(a[3]), "r"(b[0]), "r"(b[1]));
}

// split 2 floats -> packed hi bf16x2 and lo bf16x2
__device__ __forceinline__ void split2(float a, float b, uint32_t& h, uint32_t& l) {
    __nv_bfloat162 hh = __float22bfloat162_rn(make_float2(a, b));
    float2 hf = __bfloat1622float2(hh);
    __nv_bfloat162 ll = __float22bfloat162_rn(make_float2(a - hf.x, b - hf.y));
    h = *(uint32_t*)&hh;
    l = *(uint32_t*)&ll;
}

// ---------------------------------------------------------------------------
// Pipelined bf16 hi/lo HMMA GEMM. 128x128 CTA tile, K=256 in 4 stages of 64.
// SPLIT: emit bf16 hi/lo outputs; else fp32. SCATTER: shift-scatter rows.
// ---------------------------------------------------------------------------
template<int NT, bool SCATTER, bool SPLIT>
__global__ __launch_bounds__(256) void gemm_mma(
    const __nv_bfloat16* __restrict__ Ah, const __nv_bfloat16* __restrict__ Al,
    const __nv_bfloat16* __restrict__ Bh, const __nv_bfloat16* __restrict__ Bl,
    const float* __restrict__ bias, float* __restrict__ out,
    __nv_bfloat16* __restrict__ oh, __nv_bfloat16* __restrict__ ol)
{
    extern __shared__ char smem[];
    const uint32_t sb = smem_u32(smem);
    const int tid = threadIdx.x, l = tid & 31, wid = tid >> 5;
    const int mt = blockIdx.x, nb = blockIdx.y;
    const int wm = wid >> 2, wn = wid & 3;

    float* bias_s = (float*)(smem + OFF_BIAS);
    if (tid < 128) bias_s[tid] = bias[nb * 128 + tid];

    const int crow = tid >> 3;
    const int cc   = tid & 7;
    uint32_t sm_off[4];
    #pragma unroll
    for (int i = 0; i < 4; i++)
        sm_off[i] = sw128((i * 32 + crow) * 128 + cc * 16);

    const __nv_bfloat16* pAh = Ah + (size_t)(mt * 128 + crow) * CDIM + cc * 8;
    const __nv_bfloat16* pAl = Al + (size_t)(mt * 128 + crow) * CDIM + cc * 8;
    const __nv_bfloat16* pBh = Bh + (size_t)(nb * 128 + crow) * CDIM + cc * 8;
    const __nv_bfloat16* pBl = Bl + (size_t)(nb * 128 + crow) * CDIM + cc * 8;

    const int sub  = l >> 3;
    const int arl  = wm * 64 + (sub & 1) * 8 + (l & 7);
    const int acb  = (sub >> 1) * 16;
    const int lb   = l & 15;
    const int brl  = wn * 32 + (lb & 7);
    const int bcb  = (lb >> 3) * 16;

    float acc[4][4][4];
    #pragma unroll
    for (int i = 0; i < 4; i++)
        #pragma unroll
        for (int j = 0; j < 4; j++)
            #pragma unroll
            for (int r = 0; r < 4; r++) acc[i][j][r] = 0.f;

    {
        uint32_t base = sb;
        #pragma unroll
        for (int i = 0; i < 4; i++) {
            size_t g = (size_t)i * 32 * CDIM;
            cp16(base + OFF_AH + sm_off[i], pAh + g);
            cp16(base + OFF_AL + sm_off[i], pAl + g);
            cp16(base + OFF_BH + sm_off[i], pBh + g);
            cp16(base + OFF_BL + sm_off[i], pBl + g);
        }
        asm volatile("cp.async.commit_group;");
    }

    for (int kt = 0; kt < 4; kt++) {
        if (kt < 3) {
            uint32_t base = sb + ((kt + 1) & 1) * STAGE_STRIDE;
            size_t kadv = (size_t)(kt + 1) * 64;
            #pragma unroll
            for (int i = 0; i < 4; i++) {
                size_t g = (size_t)i * 32 * CDIM + kadv;
                cp16(base + OFF_AH + sm_off[i], pAh + g);
                cp16(base + OFF_AL + sm_off[i], pAl + g);
                cp16(base + OFF_BH + sm_off[i], pBh + g);
                cp16(base + OFF_BL + sm_off[i], pBl + g);
            }
            asm volatile("cp.async.commit_group;");
            asm volatile("cp.async.wait_group 1;");
        } else {
            asm volatile("cp.async.wait_group 0;");
        }
        __syncthreads();

        const uint32_t cbase = sb + (kt & 1) * STAGE_STRIDE;
        #pragma unroll
        for (int k16 = 0; k16 < 4; k16++) {
            const int k0b = k16 * 32;
            uint32_t Bhf[4][2], Blf[4][2];
            #pragma unroll
            for (int ni = 0; ni < 4; ni++) {
                uint32_t boff = sw128((brl + ni * 8) * 128 + k0b + bcb);
                ldsm2(Bhf[ni], cbase + OFF_BH + boff);
                ldsm2(Blf[ni], cbase + OFF_BL + boff);
            }
            #pragma unroll
            for (int mi = 0; mi < 4; mi++) {
                uint32_t aoff = sw128((arl + mi * 16) * 128 + k0b + acb);
                uint32_t Ahf[4], Alf[4];
                ldsm4(Ahf, cbase + OFF_AH + aoff);
                ldsm4(Alf, cbase + OFF_AL + aoff);
                #pragma unroll
                for (int ni = 0; ni < 4; ni++) {
                    mma16816(acc[mi][ni], Ahf, Bhf[ni]);
                    mma16816(acc[mi][ni], Ahf, Blf[ni]);
                    mma16816(acc[mi][ni], Alf, Bhf[ni]);
                }
            }
        }
        __syncthreads();
    }

    // epilogue via smem stage
    float* stage = (float*)smem;
    #pragma unroll
    for (int mi = 0; mi < 4; mi++)
        #pragma unroll
        for (int ni = 0; ni < 4; ni++) {
            int row = wm * 64 + mi * 16 + (l >> 2);
            int col = wn * 32 + ni * 8 + (l & 3) * 2;
            *(float2*)&stage[row * 132 + col]       = make_float2(acc[mi][ni][0], acc[mi][ni][1]);
            *(float2*)&stage[(row + 8) * 132 + col] = make_float2(acc[mi][ni][2], acc[mi][ni][3]);
        }
    __syncthreads();

    #pragma unroll
    for (int it = 0; it < 16; it++) {
        int idx = it * 256 + tid;
        int row = idx >> 5, c4 = (idx & 31) * 4;
        float4 o;
        o.x = stage[row * 132 + c4 + 0] + bias_s[c4 + 0];
        o.y = stage[row * 132 + c4 + 1] + bias_s[c4 + 1];
        o.z = stage[row * 132 + c4 + 2] + bias_s[c4 + 2];
        o.w = stage[row * 132 + c4 + 3] + bias_s[c4 + 3];
        int lrow = mt * 128 + row;
        int orow = SCATTER ? global_row(lrow >> 6, lrow & 63) : lrow;
        size_t off = (size_t)orow * NT + nb * 128 + c4;
        if (SPLIT) {
            uint32_t h0, l0, h1, l1;
            split2(o.x, o.y, h0, l0);
            split2(o.z, o.w, h1, l1);
            *(uint2*)(oh + off) = make_uint2(h0, h1);
            *(uint2*)(ol + off) = make_uint2(l0, l1);
        } else {
            *(float4*)(out + off) = o;
        }
    }
}

// ---------------------------------------------------------------------------
// Pre-pass: gather x into window order and split to bf16 hi/lo
// ---------------------------------------------------------------------------
__global__ __launch_bounds__(256) void convert_x(const float* __restrict__ x) {
    const int win = blockIdx.x;
    const int tid = threadIdx.x;
    #pragma unroll
    for (int i = 0; i < 16; i++) {
        int idx4 = i * 256 + tid;
        int row  = idx4 >> 6;
        int c4   = idx4 & 63;
        int grow = global_row(win, row);
        float4 v = *(const float4*)(x + (size_t)grow * CDIM + c4 * 4);
        uint32_t h0, h1, l0, l1;
        split2(v.x, v.y, h0, l0);
        split2(v.z, v.w, h1, l1);
        size_t o = ((size_t)win * WS2 + row) * CDIM + c4 * 4;
        *(uint2*)(g_x_hi + o) = make_uint2(h0, h1);
        *(uint2*)(g_x_lo + o) = make_uint2(l0, l1);
    }
}

__global__ void convert_w(const float* __restrict__ wq, const float* __restrict__ wo) {
    int n = blockIdx.x, k = threadIdx.x;
    if (n < QKV_N) {
        float v = wq[k * QKV_N + n];
        __nv_bfloat16 h = __float2bfloat16(v);
        g_wq_hi[n * CDIM + k] = h;
        g_wq_lo[n * CDIM + k] = __float2bfloat16(v - __bfloat162float(h));
    } else {
        int n2 = n - QKV_N;
        float v = wo[k * CDIM + n2];
        __nv_bfloat16 h = __float2bfloat16(v);
        g_wo_hi[n2 * CDIM + k] = h;
        g_wo_lo[n2 * CDIM + k] = __float2bfloat16(v - __bfloat162float(h));
    }
}

// ---------------------------------------------------------------------------
// HMMA attention. Block = (2 heads, window), 4 warps; warp = 32 q x 64 k.
// smem per local head: Q[64x(32hi|32lo)] K[...] V[...], 128B rows, SW128.
// P (exp scores) overwrites Q/K regions between QK and PV (block-synced).
// ---------------------------------------------------------------------------
__global__ __launch_bounds__(128) void attn_mma(
    const __nv_bfloat16* __restrict__ qh_g, const __nv_bfloat16* __restrict__ ql_g,
    const float* __restrict__ pos)
{
    extern __shared__ char smem[];
    const uint32_t sb = smem_u32(smem);
    const int tid = threadIdx.x, l = tid & 31, wid = tid >> 5;
    const int hg  = blockIdx.x;           // head pair 0..3
    const int win = blockIdx.y;
    const int wi  = win & 63, wy = wi >> 3, wx = wi & 7;

    // stage q/k/v (2 heads x 3 mats x 64 rows x (64B hi + 64B lo))
    #pragma unroll
    for (int i = 0; i < 24; i++) {
        int idx  = i * 128 + tid;
        int hl   = idx >= 1536;
        int rem  = idx - hl * 1536;
        int mat  = rem >> 9;
        int rem2 = rem & 511;
        int row  = rem2 >> 3;
        int ch   = rem2 & 7;
        int isHi = ch < 4;
        int c16  = ch & 3;
        uint32_t dst = sb + hl * ATT_HSTRIDE + mat * 8192
                     + sw128(row * 128 + (isHi ? 0 : 64) + c16 * 16);
        const __nv_bfloat16* src = (isHi ? qh_g : ql_g)
            + (size_t)(win * 64 + row) * QKV_N + (hg * 2 + hl) * 32 + mat * 256 + c16 * 8;
        cp16(dst, src);
    }
    asm volatile("cp.async.commit_group;");
    float* pe_s = (float*)(smem + ATT_PE_OFF);
    for (int i = tid; i < 450; i += 128) {
        int hh = i >= 225;
        pe_s[i] = pos[(hg * 2 + hh) * 225 + (i - hh * 225)];
    }
    asm volatile("cp.async.wait_group 0;");
    __syncthreads();

    const int hl = wid >> 1;              // local head
    const int w  = wid & 1;               // query half
    const uint32_t QB = sb + hl * ATT_HSTRIDE;
    const uint32_t KB = QB + 8192;
    const uint32_t VB = QB + 16384;
    const float* pe = pe_s + hl * 225;

    const int sub = l >> 3;
    const int arl = (sub & 1) * 8 + (l & 7);
    const int acb = (sub >> 1) * 16;
    const int lb  = l & 15;
    const int brl = lb & 7;
    const int bcb = (lb >> 3) * 16;

    // ---- QK^T (hi/lo 3-pass) ----
    float sc[2][8][4];
    #pragma unroll
    for (int mi = 0; mi < 2; mi++)
        #pragma unroll
        for (int ni = 0; ni < 8; ni++)
            #pragma unroll
            for (int r = 0; r < 4; r++) sc[mi][ni][r] = 0.f;

    #pragma unroll
    for (int k16 = 0; k16 < 2; k16++) {
        uint32_t Ah[2][4], Al[2][4];
        #pragma unroll
        for (int mi = 0; mi < 2; mi++) {
            uint32_t r = (w * 32 + mi * 16 + arl) * 128 + k16 * 32 + acb;
            ldsm4(Ah[mi], QB + sw128(r));
            ldsm4(Al[mi], QB + sw128(r + 64));
        }
        #pragma unroll
        for (int ni = 0; ni < 8; ni++) {
            uint32_t Bh[2], Bl[2];
            uint32_t r = (ni * 8 + brl) * 128 + k16 * 32 + bcb;
            ldsm2(Bh, KB + sw128(r));
            ldsm2(Bl, KB + sw128(r + 64));
            #pragma unroll
            for (int mi = 0; mi < 2; mi++) {
                mma16816(sc[mi][ni], Ah[mi], Bh);
                mma16816(sc[mi][ni], Ah[mi], Bl);
                mma16816(sc[mi][ni], Al[mi], Bh);
            }
        }
    }

    // ---- scale + bias + mask + softmax (rows: mi x rr, 4 lanes/row) ----
    float rinv[2][2];
    #pragma unroll
    for (int mi = 0; mi < 2; mi++)
        #pragma unroll
        for (int rr = 0; rr < 2; rr++) {
            int r  = w * 32 + mi * 16 + rr * 8 + (l >> 2);
            int qy = r >> 3, qx = r & 7;
            int gy = wy * 8 + qy, gx = wx * 8 + qx;
            int rq = (gy < 56 ? 0 : (gy < 60 ? 1 : 2)) * 3 + (gx < 56 ? 0 : (gx < 60 ? 1 : 2));
            float m = -1e30f;
            #pragma unroll
            for (int ni = 0; ni < 8; ni++)
                #pragma unroll
                for (int j = 0; j < 2; j++) {
                    int c  = ni * 8 + (l & 3) * 2 + j;
                    int ky = c >> 3, kx = c & 7;
                    int hy = wy * 8 + ky, hx = wx * 8 + kx;
                    int rk = (hy < 56 ? 0 : (hy < 60 ? 1 : 2)) * 3 + (hx < 56 ? 0 : (hx < 60 ? 1 : 2));
                    float v = sc[mi][ni][rr * 2 + j];
                    v = (rk == rq) ? v * SCALE + pe[(qy - ky + 7) * 15 + (qx - kx + 7)] : -1e30f;
                    sc[mi][ni][rr * 2 + j] = v;
                    m = fmaxf(m, v);
                }
            m = fmaxf(m, __shfl_xor_sync(0xffffffffu, m, 1));
            m = fmaxf(m, __shfl_xor_sync(0xffffffffu, m, 2));
            float s = 0.f;
            #pragma unroll
            for (int ni = 0; ni < 8; ni++)
                #pragma unroll
                for (int j = 0; j < 2; j++) {
                    float e = __expf(sc[mi][ni][rr * 2 + j] - m);
                    sc[mi][ni][rr * 2 + j] = e;
                    s += e;
                }
            s += __shfl_xor_sync(0xffffffffu, s, 1);
            s += __shfl_xor_sync(0xffffffffu, s, 2);
            rinv[mi][rr] = 1.0f / s;
        }

    // all warps done reading Q/K -> safe to overwrite with P
    __syncthreads();

    const uint32_t PH = QB + w * 4096;    // P hi over Q region
    const uint32_t PL = KB + w * 4096;    // P lo over K region
    char* smc = (char*)smem;
    #pragma unroll
    for (int mi = 0; mi < 2; mi++)
        #pragma unroll
        for (int rr = 0; rr < 2; rr++) {
            int lr = mi * 16 + rr * 8 + (l >> 2);
            #pragma unroll
            for (int ni = 0; ni < 8; ni++) {
                uint32_t h, lo;
                split2(sc[mi][ni][rr * 2], sc[mi][ni][rr * 2 + 1], h, lo);
                uint32_t off = sw128(lr * 128 + ni * 16 + (l & 3) * 4);
                *(uint32_t*)(smc + (PH - sb) + off) = h;
                *(uint32_t*)(smc + (PL - sb) + off) = lo;
            }
        }
    __syncwarp();

    // ---- P @ V (hi/lo 3-pass), V via ldmatrix.trans ----
    float o[2][4][4];
    #pragma unroll
    for (int mi = 0; mi < 2; mi++)
        #pragma unroll
        for (int nj = 0; nj < 4; nj++)
            #pragma unroll
            for (int r = 0; r < 4; r++) o[mi][nj][r] = 0.f;

    #pragma unroll
    for (int k16 = 0; k16 < 4; k16++) {
        uint32_t Ph[2][4], Pl[2][4];
        #pragma unroll
        for (int mi = 0; mi < 2; mi++) {
            uint32_t r = (mi * 16 + arl) * 128 + k16 * 32 + acb;
            ldsm4(Ph[mi], PH + sw128(r));
            ldsm4(Pl[mi], PL + sw128(r));
        }
        #pragma unroll
        for (int nj = 0; nj < 4; nj++) {
            uint32_t Vh[2], Vl[2];
            uint32_t r = (k16 * 16 + lb) * 128 + nj * 16;
            ldsm2t(Vh, VB + sw128(r));
            ldsm2t(Vl, VB + sw128(r + 64));
            #pragma unroll
            for (int mi = 0; mi < 2; mi++) {
                mma16816(o[mi][nj], Ph[mi], Vh);
                mma16816(o[mi][nj], Ph[mi], Vl);
                mma16816(o[mi][nj], Pl[mi], Vh);
            }
        }
    }

    // ---- epilogue: normalize, split, store ----
    const int head = hg * 2 + hl;
    #pragma unroll
    for (int mi = 0; mi < 2; mi++)
        #pragma unroll
        for (int rr = 0; rr < 2; rr++) {
            int r = w * 32 + mi * 16 + rr * 8 + (l >> 2);
            float inv = rinv[mi][rr];
            size_t rowoff = (size_t)(win * 64 + r) * CDIM + head * 32;
            #pragma unroll
            for (int nj = 0; nj < 4; nj++) {
                int c = nj * 8 + (l & 3) * 2;
                uint32_t h, lo;
                split2(o[mi][nj][rr * 2] * inv, o[mi][nj][rr * 2 + 1] * inv, h, lo);
                *(uint32_t*)(g_att_hi + rowoff + c) = h;
                *(uint32_t*)(g_att_lo + rowoff + c) = lo;
            }
        }
}

// ---------------------------------------------------------------------------
extern "C" void kernel_launch(void* const* d_in, const int* in_sizes, int n_in,
                              void* d_out, int out_size) {
    const float* x     = (const float*)d_in[0];
    const float* w_qkv = (const float*)d_in[1];
    const float* b_qkv = (const float*)d_in[2];
    const float* w_out = (const float*)d_in[3];
    const float* b_out = (const float*)d_in[4];
    const float* pos   = (const float*)d_in[5];
    float* out = (float*)d_out;

    __nv_bfloat16 *qh, *ql, *xh, *xl, *ah, *al, *wqh, *wql, *woh, *wol;
    cudaGetSymbolAddress((void**)&qh,  g_qkv_hi);
    cudaGetSymbolAddress((void**)&ql,  g_qkv_lo);
    cudaGetSymbolAddress((void**)&xh,  g_x_hi);
    cudaGetSymbolAddress((void**)&xl,  g_x_lo);
    cudaGetSymbolAddress((void**)&ah,  g_att_hi);
    cudaGetSymbolAddress((void**)&al,  g_att_lo);
    cudaGetSymbolAddress((void**)&wqh, g_wq_hi);
    cudaGetSymbolAddress((void**)&wql, g_wq_lo);
    cudaGetSymbolAddress((void**)&woh, g_wo_hi);
    cudaGetSymbolAddress((void**)&wol, g_wo_lo);

    cudaFuncSetAttribute(gemm_mma<QKV_N, false, true>,
                         cudaFuncAttributeMaxDynamicSharedMemorySize, SMEM_GEMM);
    cudaFuncSetAttribute(gemm_mma<CDIM, true, false>,
                         cudaFuncAttributeMaxDynamicSharedMemorySize, SMEM_GEMM);
    cudaFuncSetAttribute(attn_mma,
                         cudaFuncAttributeMaxDynamicSharedMemorySize, SMEM_ATT);

    convert_w<<<1024, 256>>>(w_qkv, w_out);
    convert_x<<<NWIN, 256>>>(x);
    gemm_mma<QKV_N, false, true><<<dim3(1024, 6), 256, SMEM_GEMM>>>(
        xh, xl, wqh, wql, b_qkv, nullptr, qh, ql);
    attn_mma<<<dim3(4, NWIN), 128, SMEM_ATT>>>(qh, ql, pos);
    gemm_mma<CDIM, true, false><<<dim3(1024, 2), 256, SMEM_GEMM>>>(
        ah, al, woh, wol, b_out, out, nullptr, nullptr);
}